// round 6
// baseline (speedup 1.0000x reference)
#include <cuda_runtime.h>

// DAGConstraintLayer: out = tree_min_project(sigmoid(x)) over (262144, 127) fp32.
// parent(i)=(i-1)/2, complete binary tree depth 7.
//
// sigmoid monotone => min(sig(a),sig(b)) = sig(min(a,b)): propagate min on raw x
// (FMNMX only), sigmoid applied once per element in the store pass.
//
// R6: ZERO block barriers. Each warp is a fully independent 3-stage pipeline
// over its own 4-row slice (508 floats = 2032 B, 16B-aligned since
// 4*127*4 = 2032 and slices start at multiples of 2032 B):
//   prefetch (warp-local cp.async) -> wait_group -> __syncwarp -> P2 -> __syncwarp -> P3
// Warps drift freely, smoothing DRAM demand; no warp ever waits on another.
//
// Hazard analysis (all warp-internal):
//  - cp.async visibility: slice written only by the warp's own lanes;
//    wait_group + __syncwarp makes it visible to all lanes.
//  - Buffer reuse: prefetch of t+2G overwrites the buffer read by this warp's
//    P2/P3 two iterations ago; the top-of-loop __syncwarp orders those reads
//    before the new cp.async writes.
//  - P2 cross-lane smem writes read by P3: middle __syncwarp.

#define NODES 127
#define ROWS_PER_TILE 32
#define ROWS_PER_WARP 4
#define THREADS 256
#define STAGES 3
#define TILE_FLOATS (ROWS_PER_TILE * NODES)    // 4064
#define WARP_FLOATS (ROWS_PER_WARP * NODES)    // 508
#define WARP_F4 (WARP_FLOATS / 4)              // 127
#define SMEM_BYTES (STAGES * TILE_FLOATS * 4)  // 48768 (< 49152 default limit)

__device__ __forceinline__ void cp_async16(void* smem_dst, const void* gmem_src) {
    unsigned s = (unsigned)__cvta_generic_to_shared(smem_dst);
    asm volatile("cp.async.cg.shared.global [%0], [%1], 16;\n" :: "r"(s), "l"(gmem_src));
}
__device__ __forceinline__ void cp_commit() {
    asm volatile("cp.async.commit_group;\n" ::: "memory");
}
template <int N>
__device__ __forceinline__ void cp_wait() {
    asm volatile("cp.async.wait_group %0;\n" :: "n"(N) : "memory");
}

__device__ __forceinline__ float fast_sigmoid(float v) {
    return __fdividef(1.0f, 1.0f + __expf(-v));  // MUFU.EX2 + MUFU.RCP
}

extern __shared__ float smem[];  // 3 tile buffers, each sliced per-warp

// Warp-local prefetch of this warp's 4-row slice of tile t.
__device__ __forceinline__ void prefetch_slice(const float* __restrict__ x,
                                               float* buf, int t,
                                               int warp, int lane) {
    const float4* __restrict__ src =
        (const float4*)(x + (size_t)t * TILE_FLOATS) + warp * WARP_F4;
    float4* dst = (float4*)buf + warp * WARP_F4;
    #pragma unroll
    for (int j = lane; j < WARP_F4; j += 32) cp_async16(dst + j, src + j);
}

__global__ void __launch_bounds__(THREADS)
dag_constraint_kernel(const float* __restrict__ x, float* __restrict__ out,
                      int ntiles) {
    const int tid  = threadIdx.x;
    const int warp = tid >> 5;
    const int lane = tid & 31;
    const int G    = gridDim.x;
    const int t0   = blockIdx.x;

    float* buf[STAGES] = { smem, smem + TILE_FLOATS, smem + 2 * TILE_FLOATS };

    // Prologue: two tiles in flight (per-warp groups).
    if (t0 < ntiles) prefetch_slice(x, buf[0], t0, warp, lane);
    cp_commit();
    if (t0 + G < ntiles) prefetch_slice(x, buf[1], t0 + G, warp, lane);
    cp_commit();

    // P2 lane mapping (loop-invariant): lane -> (row in slice, level-3 subtree).
    const int row = lane & 3;
    const int sub = lane >> 2;         // 0..7
    const int n1 = 1 + (sub >> 2);     // node 1 or 2
    const int n2 = 3 + (sub >> 1);     // nodes 3..6
    const int n3 = 7 + sub;            // nodes 7..14 (unique per sub)
    const int b4 = 15 + 2 * sub;
    const int b5 = 31 + 4 * sub;
    const int b6 = 63 + 8 * sub;
    const int rowbase = (warp * ROWS_PER_WARP + row) * NODES;

    int stage = 0;
    for (int t = t0; t < ntiles; t += G) {
        cp_wait<1>();        // this warp's group for tile t retired
        __syncwarp();        // (a) cp.async data visible to all lanes
                             // (b) prior iter's P3 reads ordered before refill

        // Refill the buffer this warp consumed two iterations ago.
        const int pf = t + 2 * G;
        const int ps = stage + 2 >= STAGES ? stage + 2 - STAGES : stage + 2;
        if (pf < ntiles) prefetch_slice(x, buf[ps], pf, warp, lane);
        cp_commit();         // uniform per-thread group counting

        float* cur = buf[stage];
        float* r = cur + rowbase;

        // ---- P2: divergence-free min-propagation on raw x ----
        {
            const float v0 = r[0];                       // node 0: read-only
            const float v1 = fminf(r[n1], v0);           // lockstep read, then
            if ((sub & 3) == 0) r[n1] = v1;              //   designated write
            const float v2 = fminf(r[n2], v1);
            if ((sub & 1) == 0) r[n2] = v2;
            const float v3 = fminf(r[n3], v2);
            r[n3] = v3;
            const float a0 = fminf(r[b4 + 0], v3); r[b4 + 0] = a0;
            const float a1 = fminf(r[b4 + 1], v3); r[b4 + 1] = a1;
            const float c0 = fminf(r[b5 + 0], a0); r[b5 + 0] = c0;
            const float c1 = fminf(r[b5 + 1], a0); r[b5 + 1] = c1;
            const float c2 = fminf(r[b5 + 2], a1); r[b5 + 2] = c2;
            const float c3 = fminf(r[b5 + 3], a1); r[b5 + 3] = c3;
            r[b6 + 0] = fminf(r[b6 + 0], c0);
            r[b6 + 1] = fminf(r[b6 + 1], c0);
            r[b6 + 2] = fminf(r[b6 + 2], c1);
            r[b6 + 3] = fminf(r[b6 + 3], c1);
            r[b6 + 4] = fminf(r[b6 + 4], c2);
            r[b6 + 5] = fminf(r[b6 + 5], c2);
            r[b6 + 6] = fminf(r[b6 + 6], c3);
            r[b6 + 7] = fminf(r[b6 + 7], c3);
        }
        __syncwarp();        // P2 cross-lane writes -> P3 reads

        // ---- P3: sigmoid + coalesced streaming store (warp's slice) ----
        {
            const float4* s4 = (const float4*)cur + warp * WARP_F4;
            float4* __restrict__ gout =
                (float4*)(out + (size_t)t * TILE_FLOATS) + warp * WARP_F4;
            #pragma unroll
            for (int j = lane; j < WARP_F4; j += 32) {
                float4 v = s4[j];
                v.x = fast_sigmoid(v.x);
                v.y = fast_sigmoid(v.y);
                v.z = fast_sigmoid(v.z);
                v.w = fast_sigmoid(v.w);
                __stcs(gout + j, v);
            }
        }
        stage = stage + 1 >= STAGES ? 0 : stage + 1;
    }
}

extern "C" void kernel_launch(void* const* d_in, const int* in_sizes, int n_in,
                              void* d_out, int out_size) {
    const float* x = (const float*)d_in[0];
    float* out = (float*)d_out;

    const int total = in_sizes[0];              // 262144 * 127
    const int rows = total / NODES;             // 262144
    const int ntiles = rows / ROWS_PER_TILE;    // 8192

    int grid = 148 * 4;                         // 4 CTAs/SM (48.8 KB smem each)
    if (grid > ntiles) grid = ntiles;

    dag_constraint_kernel<<<grid, THREADS, SMEM_BYTES>>>(x, out, ntiles);
}

// round 7
// speedup vs baseline: 1.1287x; 1.1287x over previous
#include <cuda_runtime.h>

// DAGConstraintLayer: out = tree_min_project(sigmoid(x)) over (262144, 127) fp32.
// parent(i)=(i-1)/2, complete binary tree depth 7.
//
// sigmoid monotone => min(sig(a),sig(b)) = sig(min(a,b)): propagate min on raw x
// (FMNMX only), sigmoid applied once per element in the store pass.
//
// R7 = R3's occupancy + R6's zero-barrier warp-local pipeline.
//  - 2-stage ring, 32-row tiles (16256 B) -> 32.5 KB smem -> 7 CTAs/SM, 56 warps
//    (R3-proven residency; rounds 4-6 showed DRAM% tracks warps/SM).
//  - Each warp owns a 4-row slice (508 floats, 2032 B, 16B-aligned) in every
//    buffer: warp-local cp.async prefetch, P2 min-propagation, P3 sigmoid+store.
//    No __syncthreads anywhere.
//  - Loop order: prefetch t+G (into the buffer whose t-G contents this warp
//    fully consumed) -> commit -> wait<1> (t ready) -> __syncwarp -> P2 ->
//    __syncwarp -> P3. The t+G group stays in flight through all of P2+P3.
//
// Hazards (all warp- or lane-local):
//  - buffer reuse: P3 lane j-offsets == prefetch lane j-offsets, so each lane
//    overwrites only what it itself read; per-lane program order suffices.
//  - cp.async cross-lane visibility: each lane waits its own group, then
//    __syncwarp (has fence semantics) publishes all lanes' arrivals.
//  - P2 cross-lane smem writes -> P3 reads: middle __syncwarp.

#define NODES 127
#define ROWS_PER_TILE 32
#define ROWS_PER_WARP 4
#define THREADS 256
#define TILE_FLOATS (ROWS_PER_TILE * NODES)    // 4064
#define WARP_FLOATS (ROWS_PER_WARP * NODES)    // 508
#define WARP_F4 (WARP_FLOATS / 4)              // 127
#define SMEM_BYTES (2 * TILE_FLOATS * 4)       // 32512 -> 7 CTAs/SM

__device__ __forceinline__ void cp_async16(void* smem_dst, const void* gmem_src) {
    unsigned s = (unsigned)__cvta_generic_to_shared(smem_dst);
    asm volatile("cp.async.cg.shared.global [%0], [%1], 16;\n" :: "r"(s), "l"(gmem_src));
}
__device__ __forceinline__ void cp_commit() {
    asm volatile("cp.async.commit_group;\n" ::: "memory");
}
template <int N>
__device__ __forceinline__ void cp_wait() {
    asm volatile("cp.async.wait_group %0;\n" :: "n"(N) : "memory");
}

__device__ __forceinline__ float fast_sigmoid(float v) {
    return __fdividef(1.0f, 1.0f + __expf(-v));  // MUFU.EX2 + MUFU.RCP
}

extern __shared__ float smem[];  // 2 tile buffers, per-warp sliced

__device__ __forceinline__ void prefetch_slice(const float* __restrict__ x,
                                               float* buf, int t,
                                               int warp, int lane) {
    const float4* __restrict__ src =
        (const float4*)(x + (size_t)t * TILE_FLOATS) + warp * WARP_F4;
    float4* dst = (float4*)buf + warp * WARP_F4;
    #pragma unroll
    for (int j = lane; j < WARP_F4; j += 32) cp_async16(dst + j, src + j);
}

__global__ void __launch_bounds__(THREADS)
dag_constraint_kernel(const float* __restrict__ x, float* __restrict__ out,
                      int ntiles) {
    const int tid  = threadIdx.x;
    const int warp = tid >> 5;
    const int lane = tid & 31;
    const int G    = gridDim.x;
    const int t0   = blockIdx.x;

    float* buf0 = smem;
    float* buf1 = smem + TILE_FLOATS;

    // Prologue: tile t0 in flight.
    if (t0 < ntiles) prefetch_slice(x, buf0, t0, warp, lane);
    cp_commit();

    // P2 lane mapping (loop-invariant): lane -> (row in slice, level-3 subtree).
    const int row = lane & 3;
    const int sub = lane >> 2;         // 0..7
    const int n1 = 1 + (sub >> 2);     // node 1 or 2
    const int n2 = 3 + (sub >> 1);     // nodes 3..6
    const int n3 = 7 + sub;            // nodes 7..14 (unique per sub)
    const int b4 = 15 + 2 * sub;
    const int b5 = 31 + 4 * sub;
    const int b6 = 63 + 8 * sub;
    const int rowbase = (warp * ROWS_PER_WARP + row) * NODES;

    int stage = 0;
    for (int t = t0; t < ntiles; t += G) {
        float* cur = stage ? buf1 : buf0;
        float* oth = stage ? buf0 : buf1;

        // Prefetch t+G into 'oth' (this warp's lanes fully consumed its t-G
        // contents at matching offsets last iteration; lane-local ordering).
        const int pf = t + G;
        if (pf < ntiles) prefetch_slice(x, oth, pf, warp, lane);
        cp_commit();         // uniform group counting even when empty

        cp_wait<1>();        // tile t's group retired; t+G stays in flight
        __syncwarp();        // publish all lanes' cp.async arrivals warp-wide

        float* r = cur + rowbase;

        // ---- P2: divergence-free min-propagation on raw x ----
        {
            const float v0 = r[0];                       // node 0: read-only
            const float v1 = fminf(r[n1], v0);           // lockstep read, then
            if ((sub & 3) == 0) r[n1] = v1;              //   designated write
            const float v2 = fminf(r[n2], v1);
            if ((sub & 1) == 0) r[n2] = v2;
            const float v3 = fminf(r[n3], v2);
            r[n3] = v3;
            const float a0 = fminf(r[b4 + 0], v3); r[b4 + 0] = a0;
            const float a1 = fminf(r[b4 + 1], v3); r[b4 + 1] = a1;
            const float c0 = fminf(r[b5 + 0], a0); r[b5 + 0] = c0;
            const float c1 = fminf(r[b5 + 1], a0); r[b5 + 1] = c1;
            const float c2 = fminf(r[b5 + 2], a1); r[b5 + 2] = c2;
            const float c3 = fminf(r[b5 + 3], a1); r[b5 + 3] = c3;
            r[b6 + 0] = fminf(r[b6 + 0], c0);
            r[b6 + 1] = fminf(r[b6 + 1], c0);
            r[b6 + 2] = fminf(r[b6 + 2], c1);
            r[b6 + 3] = fminf(r[b6 + 3], c1);
            r[b6 + 4] = fminf(r[b6 + 4], c2);
            r[b6 + 5] = fminf(r[b6 + 5], c2);
            r[b6 + 6] = fminf(r[b6 + 6], c3);
            r[b6 + 7] = fminf(r[b6 + 7], c3);
        }
        __syncwarp();        // P2 cross-lane writes -> P3 reads

        // ---- P3: sigmoid + coalesced streaming store (warp's slice) ----
        {
            const float4* s4 = (const float4*)cur + warp * WARP_F4;
            float4* __restrict__ gout =
                (float4*)(out + (size_t)t * TILE_FLOATS) + warp * WARP_F4;
            #pragma unroll
            for (int j = lane; j < WARP_F4; j += 32) {
                float4 v = s4[j];
                v.x = fast_sigmoid(v.x);
                v.y = fast_sigmoid(v.y);
                v.z = fast_sigmoid(v.z);
                v.w = fast_sigmoid(v.w);
                __stcs(gout + j, v);
            }
        }
        stage ^= 1;
    }
}

extern "C" void kernel_launch(void* const* d_in, const int* in_sizes, int n_in,
                              void* d_out, int out_size) {
    const float* x = (const float*)d_in[0];
    float* out = (float*)d_out;

    const int total = in_sizes[0];              // 262144 * 127
    const int rows = total / NODES;             // 262144
    const int ntiles = rows / ROWS_PER_TILE;    // 8192

    int grid = 148 * 7;                         // 7 CTAs/SM, 56 warps/SM
    if (grid > ntiles) grid = ntiles;

    dag_constraint_kernel<<<grid, THREADS, SMEM_BYTES>>>(x, out, ntiles);
}

// round 8
// speedup vs baseline: 1.1388x; 1.0089x over previous
#include <cuda_runtime.h>

// DAGConstraintLayer: out = tree_min_project(sigmoid(x)) over (262144, 127) fp32.
// parent(i)=(i-1)/2, complete binary tree depth 7.
//
// sigmoid monotone => min(sig(a),sig(b)) = sig(min(a,b)): propagate min on raw x,
// sigmoid applied once per element at store time.
//
// R8: pure register/shuffle kernel - NO shared memory, NO barriers, NO cp.async.
// One warp processes one row entirely in registers:
//   lane l holds nodes l (v0), 32+l (v1), 64+l (v2), 96+l (v3, lanes 0..30).
// Min-propagation via warp shuffles:
//   A) v0 (nodes 0..31 = levels 0..4 + node 31): 5 level-steps, each
//      p = shfl(v0, (l-1)>>1); lanes at that level take min. Parents are always
//      finalized by the preceding step.
//   B) v1 (nodes 32..63): parent (31+l)>>1 in {15..31}, all in v0. 1 shuffle.
//   C) v2 (nodes 64..95): parent (63+l)>>1 in {31..47}: v0@31 for l=0 else
//      v1@((63+l)>>1 - 32). 2 shuffles + select.
//   D) v3 (nodes 96..126): parent (95+l)>>1 in {47..62}, all in v1. 1 shuffle.
// 2 rows per loop iteration -> 8 outstanding 128B LDGs per warp for MLP.
// Rows are 508 B so the 128 B accesses are misaligned; overlapping sectors are
// shared with neighboring rows through L2 (no extra DRAM traffic).

#define NODES 127

__device__ __forceinline__ float fast_sigmoid(float v) {
    return __fdividef(1.0f, 1.0f + __expf(-v));  // MUFU.EX2 + MUFU.RCP
}

// In-register tree min-propagation for one row held across the warp.
__device__ __forceinline__ void row_minprop(float& v0, float& v1, float& v2,
                                            float& v3, int lane) {
    const unsigned FULL = 0xffffffffu;
    const int plA = (lane > 0) ? ((lane - 1) >> 1) : 0;

    // A: levels 1..5 inside v0. Step L finalizes nodes (2^L-1 .. 2^{L+1}-2)&<=31.
    #pragma unroll
    for (int L = 1; L <= 5; ++L) {
        float p = __shfl_sync(FULL, v0, plA);
        const int lo = (1 << L) - 1;
        const int hi = (2 << L) - 2;
        if (lane >= lo && lane <= hi) v0 = fminf(v0, p);
    }
    // B: nodes 32..63 <- parents 15..31 (v0). (node 63's parent is 31: (31+31)>>1=31 ok)
    v1 = fminf(v1, __shfl_sync(FULL, v0, (31 + lane) >> 1));
    // C: nodes 64..95 <- parents 31..47.
    {
        float pa = __shfl_sync(FULL, v1, (((63 + lane) >> 1) - 32) & 31);
        float pb = __shfl_sync(FULL, v0, 31);
        v2 = fminf(v2, (lane == 0) ? pb : pa);
    }
    // D: nodes 96..126 <- parents 47..62 (v1 lanes 15..30). lane31's v3 unused.
    v3 = fminf(v3, __shfl_sync(FULL, v1, ((95 + lane) >> 1) - 32));
}

__global__ void __launch_bounds__(256)
dag_constraint_kernel(const float* __restrict__ x, float* __restrict__ out,
                      int nrows) {
    const int lane = threadIdx.x & 31;
    const int gw   = (blockIdx.x * blockDim.x + threadIdx.x) >> 5;  // global warp
    const int nw   = (gridDim.x * blockDim.x) >> 5;                 // total warps
    const bool hasv3 = (lane < 31);

    for (int r = gw * 2; r < nrows; r += nw * 2) {
        // ---- load two rows (8 coalesced 128B LDGs in flight) ----
        const float* a = x + (size_t)r * NODES;
        float a0 = a[lane];
        float a1 = a[32 + lane];
        float a2 = a[64 + lane];
        float a3 = hasv3 ? a[96 + lane] : 0.0f;

        const int r2 = r + 1;
        const bool has2 = (r2 < nrows);
        const float* b = x + (size_t)(has2 ? r2 : r) * NODES;
        float b0 = b[lane];
        float b1 = b[32 + lane];
        float b2 = b[64 + lane];
        float b3 = hasv3 ? b[96 + lane] : 0.0f;

        // ---- min-propagation (register/shuffle only) ----
        row_minprop(a0, a1, a2, a3, lane);
        row_minprop(b0, b1, b2, b3, lane);

        // ---- sigmoid + store ----
        float* oa = out + (size_t)r * NODES;
        oa[lane]      = fast_sigmoid(a0);
        oa[32 + lane] = fast_sigmoid(a1);
        oa[64 + lane] = fast_sigmoid(a2);
        if (hasv3) oa[96 + lane] = fast_sigmoid(a3);

        if (has2) {
            float* ob = out + (size_t)r2 * NODES;
            ob[lane]      = fast_sigmoid(b0);
            ob[32 + lane] = fast_sigmoid(b1);
            ob[64 + lane] = fast_sigmoid(b2);
            if (hasv3) ob[96 + lane] = fast_sigmoid(b3);
        }
    }
}

extern "C" void kernel_launch(void* const* d_in, const int* in_sizes, int n_in,
                              void* d_out, int out_size) {
    const float* x = (const float*)d_in[0];
    float* out = (float*)d_out;

    const int total = in_sizes[0];      // 262144 * 127
    const int nrows = total / NODES;    // 262144

    // Persistent-style grid: plenty of independent warps, ~18 row-pairs each.
    int grid = 148 * 6;
    dag_constraint_kernel<<<grid, 256>>>(x, out, nrows);
}